// round 7
// baseline (speedup 1.0000x reference)
#include <cuda_runtime.h>
#include <cstdint>
#include <cstddef>

// Problem dims
#define TT 1024
#define BB 64
#define HH 256
#define WPADI 260   // wih SMEM row stride (floats)

// Fused persistent kernel. 128 CTAs = 2 dirs x 8 grps x 8 slices.
// CTA: 32 hidden (96 gate rows) x 8 batches, K=256 for both GEMMs.
// Thread (jg 0..31, ks 0..7): 3 gate rows x 32-k slice.
// Step pipeline: poll flags -> cp.async h(s-1)+x(s+1) -> gx GEMM (overlaps
// the async copies) -> wait+sync -> rec GEMM -> reduce -> pointwise ->
// publish h -> release flag.

__device__ float    g_h[2][2][8][8][256];   // [dir][buf][grp][b][k]
__device__ unsigned g_flag[2][8][8];        // per (dir,grp,slice) step flag
__device__ unsigned g_cnt[16 * 32];         // init barrier (128B-strided)
__device__ unsigned g_phs[16 * 32];

// ---------------------------------------------------------------------------
// Helpers
// ---------------------------------------------------------------------------
__device__ __forceinline__ unsigned long long ffma2(
    unsigned long long a, unsigned long long b, unsigned long long c) {
    unsigned long long d;
    asm("fma.rn.f32x2 %0, %1, %2, %3;" : "=l"(d) : "l"(a), "l"(b), "l"(c));
    return d;
}
__device__ __forceinline__ float pair_sum(unsigned long long p) {
    float lo, hi;
    asm("mov.b64 {%0, %1}, %2;" : "=f"(lo), "=f"(hi) : "l"(p));
    return lo + hi;
}
__device__ __forceinline__ float fast_sigmoid(float x) {
    return 1.0f / (1.0f + __expf(-x));
}
__device__ __forceinline__ float fast_tanh(float x) {
    return 2.0f / (1.0f + __expf(-2.0f * x)) - 1.0f;
}
__device__ __forceinline__ uint32_t smem_u32(const void* p) {
    uint32_t a;
    asm("{ .reg .u64 t; cvta.to.shared.u64 t, %1; cvt.u32.u64 %0, t; }"
        : "=r"(a) : "l"(p));
    return a;
}
__device__ __forceinline__ void cp_async16(uint32_t dst, const void* src) {
    asm volatile("cp.async.cg.shared.global [%0], [%1], 16;"
                 :: "r"(dst), "l"(src) : "memory");
}
#define CP_COMMIT() asm volatile("cp.async.commit_group;" ::: "memory")
#define CP_WAIT0()  asm volatile("cp.async.wait_group 0;" ::: "memory")

// float4-chunk swizzle within a 256-float row (64 chunks).
__device__ __forceinline__ int swz(int q) {
    return (q & ~7) | ((q ^ (q >> 3)) & 7);
}

// One-time replay-safe group barrier (phase monotonic across replays).
__device__ __forceinline__ void grp_barrier_init(int gi) {
    __syncthreads();
    if (threadIdx.x == 0) {
        unsigned* cnt = &g_cnt[gi * 32];
        unsigned* phs = &g_phs[gi * 32];
        unsigned ph;
        asm volatile("ld.acquire.gpu.global.u32 %0, [%1];"
                     : "=r"(ph) : "l"(phs) : "memory");
        unsigned prev;
        asm volatile("atom.acq_rel.gpu.global.add.u32 %0, [%1], %2;"
                     : "=r"(prev) : "l"(cnt), "r"(1u) : "memory");
        if (prev == 7u) {
            asm volatile("st.relaxed.gpu.global.u32 [%0], %1;"
                         :: "l"(cnt), "r"(0u) : "memory");
            asm volatile("red.release.gpu.global.add.u32 [%0], %1;"
                         :: "l"(phs), "r"(1u) : "memory");
        } else {
            unsigned cur;
            do {
                asm volatile("ld.acquire.gpu.global.u32 %0, [%1];"
                             : "=r"(cur) : "l"(phs) : "memory");
            } while (cur == ph);
        }
    }
    __syncthreads();
}

// ---------------------------------------------------------------------------
// Fused persistent LSTM kernel. grid=128, block=256.
// ---------------------------------------------------------------------------
__global__ void __launch_bounds__(256, 1) lstm_fused(
    const float* __restrict__ X,
    const float* __restrict__ wih_f, const float* __restrict__ whh_f,
    const float* __restrict__ bih_f, const float* __restrict__ bhh_f,
    const float* __restrict__ wih_b, const float* __restrict__ whh_b,
    const float* __restrict__ bih_b, const float* __restrict__ bhh_b,
    float* __restrict__ out)
{
    extern __shared__ float sm[];
    float* wih_s = sm;                       // 96 * WPADI
    float* hs    = sm + 96 * WPADI;          // 2 * 8 * 256
    float* xs    = hs + 2 * 8 * 256;         // 2 * 8 * 256

    const int bx  = blockIdx.x;
    const int dir = bx >> 6;
    const int grp = (bx >> 3) & 7;
    const int sl  = bx & 7;
    const int j0  = sl * 32;
    const int gi  = dir * 8 + grp;

    const float* whh = dir ? whh_b : whh_f;
    const float* wih = dir ? wih_b : wih_f;
    const float* bih = dir ? bih_b : bih_f;
    const float* bhh = dir ? bhh_b : bhh_f;

    const int tid  = threadIdx.x;
    const int lane = tid & 31;
    const int warp = tid >> 5;
    const int jg   = warp * 4 + (lane >> 3);   // hidden within slice 0..31
    const int ks   = lane & 7;                 // k-slice 0..7
    const int j    = j0 + jg;
    const int bG   = grp * 8 + ks;             // this thread's output batch
    const int col  = ks * 32;                  // k-slice base column

    // Per-thread staging indices (2 float4 per thread for h and x).
    const int f0b = tid >> 6,          f0q = tid & 63;
    const int f1b = (tid + 256) >> 6,  f1q = (tid + 256) & 63;
    const int d0  = f0b * 256 + swz(f0q) * 4;
    const int d1  = f1b * 256 + swz(f1q) * 4;
    const uint32_t hs_u = smem_u32(hs);
    const uint32_t xs_u = smem_u32(xs);

    // --- W_hh slice into REGISTERS: 3 rows x 32 k = 48 f32x2. ---
    unsigned long long w0r[16], w1r[16], w2r[16];
#pragma unroll
    for (int g = 0; g < 3; g++) {
        const float* base = whh + (size_t)(g * 256 + j) * 256 + col;
        unsigned long long* dst = (g == 0) ? w0r : (g == 1) ? w1r : w2r;
#pragma unroll
        for (int c = 0; c < 8; c++) {
            ulonglong2 wv = *(const ulonglong2*)(base + c * 4);
            dst[2 * c]     = wv.x;
            dst[2 * c + 1] = wv.y;
        }
    }

    // --- W_ih slice into SMEM (swizzled 16B chunks). ---
    for (int idx = tid; idx < 96 * 64; idx += 256) {
        int r = idx >> 6, q = idx & 63;
        int grow = (r >> 5) * 256 + j0 + (r & 31);
        float4 v = *(const float4*)(wih + (size_t)grow * 256 + q * 4);
        *(float4*)(wih_s + r * WPADI + swz(q) * 4) = v;
    }

    const float bias0 = bih[j]       + bhh[j];
    const float bias1 = bih[256 + j] + bhh[256 + j];
    const float bias2 = bih[512 + j] + bhh[512 + j];

    // Zero h buffer 0; stage x for t0 into xs buffer 0.
    for (int idx = tid; idx < 8 * 256; idx += 256) hs[idx] = 0.0f;
    {
        const int t0 = dir ? (TT - 1) : 0;
        float4 v0 = __ldcg((const float4*)(
            X + ((size_t)(grp * 8 + f0b) * TT + t0) * 256 + f0q * 4));
        float4 v1 = __ldcg((const float4*)(
            X + ((size_t)(grp * 8 + f1b) * TT + t0) * 256 + f1q * 4));
        *(float4*)(xs + d0) = v0;
        *(float4*)(xs + d1) = v1;
    }
    if (tid == 0)
        asm volatile("st.relaxed.gpu.global.u32 [%0], %1;"
                     :: "l"(&g_flag[dir][grp][sl]), "r"(0u) : "memory");
    grp_barrier_init(gi);

    float c_reg = 0.0f;

    for (int s = 0; s < TT; s++) {
        const int t = dir ? (TT - 1 - s) : s;

        // --- Kick x(s+1) prefetch (cp.async, no regs held). ---
        if (s + 1 < TT) {
            const int tn = dir ? (t - 1) : (t + 1);
            const uint32_t xd = xs_u + (((s + 1) & 1) * 2048) * 4;
            cp_async16(xd + d0 * 4,
                X + ((size_t)(grp * 8 + f0b) * TT + tn) * 256 + f0q * 4);
            cp_async16(xd + d1 * 4,
                X + ((size_t)(grp * 8 + f1b) * TT + tn) * 256 + f1q * 4);
        }

        // --- Poll peer flags (set at end of their step s-1), then cp.async h. ---
        if (s > 0) {
            if (tid < 8) {
                const unsigned* f = &g_flag[dir][grp][tid];
                unsigned v;
                do {
                    asm volatile("ld.acquire.gpu.global.u32 %0, [%1];"
                                 : "=r"(v) : "l"(f) : "memory");
                } while (v < (unsigned)s);
            }
            __syncthreads();   // flags confirmed CTA-wide
            const float* src = &g_h[dir][s & 1][grp][0][0];
            const uint32_t hd = hs_u + ((s & 1) * 2048) * 4;
            cp_async16(hd + d0 * 4, src + tid * 4);
            cp_async16(hd + d1 * 4, src + (tid + 256) * 4);
        }
        CP_COMMIT();

        // --- gx GEMM: W_ih (SMEM) x x[t] (SMEM) — overlaps the copies. ---
        unsigned long long P0[8], P1[8], P2[8];
#pragma unroll
        for (int b = 0; b < 8; b++) { P0[b] = 0ull; P1[b] = 0ull; P2[b] = 0ull; }

        const float* xb = xs + (s & 1) * 2048;
#pragma unroll
        for (int c = 0; c < 8; c++) {
            const int off = col + ((c ^ ks) & 7) * 4;
            ulonglong2 w0 = *(const ulonglong2*)(wih_s + (jg)      * WPADI + off);
            ulonglong2 w1 = *(const ulonglong2*)(wih_s + (32 + jg) * WPADI + off);
            ulonglong2 w2 = *(const ulonglong2*)(wih_s + (64 + jg) * WPADI + off);
#pragma unroll
            for (int b = 0; b < 8; b++) {
                ulonglong2 hv = *(const ulonglong2*)(xb + b * 256 + off);
                P0[b] = ffma2(w0.x, hv.x, P0[b]);
                P1[b] = ffma2(w1.x, hv.x, P1[b]);
                P2[b] = ffma2(w2.x, hv.x, P2[b]);
                P0[b] = ffma2(w0.y, hv.y, P0[b]);
                P1[b] = ffma2(w1.y, hv.y, P1[b]);
                P2[b] = ffma2(w2.y, hv.y, P2[b]);
            }
        }

        // --- Copies done? (h landed during gx) ---
        CP_WAIT0();
        __syncthreads();

        // --- Recurrent GEMM: W_hh (regs) x h (SMEM), same accumulators. ---
        const float* hb = hs + (s & 1) * 2048;
#pragma unroll
        for (int b = 0; b < 8; b++) {
            const float* hp = hb + b * 256 + col;
#pragma unroll
            for (int c = 0; c < 8; c++) {
                ulonglong2 hv = *(const ulonglong2*)(hp + ((c ^ ks) & 7) * 4);
                P0[b] = ffma2(w0r[2 * c], hv.x, P0[b]);
                P1[b] = ffma2(w1r[2 * c], hv.x, P1[b]);
                P2[b] = ffma2(w2r[2 * c], hv.x, P2[b]);
                P0[b] = ffma2(w0r[2 * c + 1], hv.y, P0[b]);
                P1[b] = ffma2(w1r[2 * c + 1], hv.y, P1[b]);
                P2[b] = ffma2(w2r[2 * c + 1], hv.y, P2[b]);
            }
        }

        float a0[8], a1[8], a2[8];
#pragma unroll
        for (int b = 0; b < 8; b++) {
            a0[b] = pair_sum(P0[b]);
            a1[b] = pair_sum(P1[b]);
            a2[b] = pair_sum(P2[b]);
        }

        // --- Butterfly reduce-scatter over ks: lane ks owns batch b=ks. ---
        const bool hi4 = (ks & 4) != 0;
        float t0a[4], t1a[4], t2a[4];
#pragma unroll
        for (int i = 0; i < 4; i++) {
            float s0 = hi4 ? a0[i] : a0[i + 4];
            float s1 = hi4 ? a1[i] : a1[i + 4];
            float s2 = hi4 ? a2[i] : a2[i + 4];
            t0a[i] = (hi4 ? a0[i + 4] : a0[i]) + __shfl_xor_sync(0xffffffffu, s0, 4);
            t1a[i] = (hi4 ? a1[i + 4] : a1[i]) + __shfl_xor_sync(0xffffffffu, s1, 4);
            t2a[i] = (hi4 ? a2[i + 4] : a2[i]) + __shfl_xor_sync(0xffffffffu, s2, 4);
        }
        const bool hi2 = (ks & 2) != 0;
        float u0[2], u1[2], u2[2];
#pragma unroll
        for (int i = 0; i < 2; i++) {
            float s0 = hi2 ? t0a[i] : t0a[i + 2];
            float s1 = hi2 ? t1a[i] : t1a[i + 2];
            float s2 = hi2 ? t2a[i] : t2a[i + 2];
            u0[i] = (hi2 ? t0a[i + 2] : t0a[i]) + __shfl_xor_sync(0xffffffffu, s0, 2);
            u1[i] = (hi2 ? t1a[i + 2] : t1a[i]) + __shfl_xor_sync(0xffffffffu, s1, 2);
            u2[i] = (hi2 ? t2a[i + 2] : t2a[i]) + __shfl_xor_sync(0xffffffffu, s2, 2);
        }
        const bool hi1 = (ks & 1) != 0;
        float s0 = hi1 ? u0[0] : u0[1];
        float s1 = hi1 ? u1[0] : u1[1];
        float s2 = hi1 ? u2[0] : u2[1];
        float f0 = (hi1 ? u0[1] : u0[0]) + __shfl_xor_sync(0xffffffffu, s0, 1);
        float f1 = (hi1 ? u1[1] : u1[0]) + __shfl_xor_sync(0xffffffffu, s1, 1);
        float f2 = (hi1 ? u2[1] : u2[0]) + __shfl_xor_sync(0xffffffffu, s2, 1);

        f0 += bias0; f1 += bias1; f2 += bias2;

        // --- Coupled-gate pointwise for (hidden j, batch bG). ---
        float ig = fast_sigmoid(f0);
        float cg = fast_tanh(f1);
        float og = fast_sigmoid(f2);
        c_reg = (1.0f - ig) * c_reg + ig * cg;
        float h = og * fast_tanh(c_reg);

        if (s == TT - 1) {
            out[(size_t)t * (BB * 2 * HH) + (size_t)bG * (2 * HH)
                + dir * HH + j] = h;
            size_t base = (size_t)TT * BB * 2 * HH;
            out[base + (size_t)bG * (2 * HH) + dir * HH + j] = h;
            out[base + (size_t)BB * 2 * HH + (size_t)bG * (2 * HH)
                + dir * HH + j] = c_reg;
        } else {
            // Publish h slice; sync; release flag; stream output store.
            g_h[dir][(s + 1) & 1][grp][ks][j] = h;
            __syncthreads();
            if (tid == 0)
                asm volatile("st.release.gpu.global.u32 [%0], %1;"
                             :: "l"(&g_flag[dir][grp][sl]),
                                "r"((unsigned)(s + 1)) : "memory");
            out[(size_t)t * (BB * 2 * HH) + (size_t)bG * (2 * HH)
                + dir * HH + j] = h;
        }
    }
}

// ---------------------------------------------------------------------------
// Launch. Inputs: X, wih_f, whh_f, bih_f, bhh_f, wih_b, whh_b, bih_b, bhh_b.
// Output fp32: out[T,B,2H] ++ hn[1,B,2H] ++ cn[1,B,2H].
// ---------------------------------------------------------------------------
extern "C" void kernel_launch(void* const* d_in, const int* in_sizes, int n_in,
                              void* d_out, int out_size) {
    const float* X     = (const float*)d_in[0];
    const float* wih_f = (const float*)d_in[1];
    const float* whh_f = (const float*)d_in[2];
    const float* bih_f = (const float*)d_in[3];
    const float* bhh_f = (const float*)d_in[4];
    const float* wih_b = (const float*)d_in[5];
    const float* whh_b = (const float*)d_in[6];
    const float* bih_b = (const float*)d_in[7];
    const float* bhh_b = (const float*)d_in[8];
    float* out = (float*)d_out;

    const int smem = (96 * WPADI + 2 * 8 * 256 + 2 * 8 * 256) * (int)sizeof(float);
    cudaFuncSetAttribute(lstm_fused, cudaFuncAttributeMaxDynamicSharedMemorySize,
                         smem);

    lstm_fused<<<128, 256, smem>>>(X, wih_f, whh_f, bih_f, bhh_f,
                                   wih_b, whh_b, bih_b, bhh_b, out);
}